// round 15
// baseline (speedup 1.0000x reference)
#include <cuda_runtime.h>
#include <math_constants.h>

#define BB      8
#define HDIM    4096
#define NHEADS  32
#define HD      128
#define N3      12288          // 3*HDIM
#define KS1     32             // K-splits for qkv gemm
#define KC1     (HDIM / KS1)   // 128 -> 32 stages of 4 rows
#define KS2     64             // K-splits for proj gemm
#define KC2     (HDIM / KS2)   // 64  -> 16 stages
#define TSPLIT  8              // T-splits for flash decode
#define CHUNK_MAX 256          // ceil(2048 / TSPLIT)

// ---------------- scratch (allocation-free) ----------------
__device__ __align__(16) float g_qkv_part[(size_t)KS1 * BB * N3];    // 12.6 MB
__device__ __align__(16) float g_qkv[BB * N3];
__device__ __align__(16) float g_proj_part[(size_t)KS2 * BB * HDIM]; // 8.4 MB
__device__ __align__(16) float g_pm[BB * NHEADS * TSPLIT];
__device__ __align__(16) float g_pl[BB * NHEADS * TSPLIT];
__device__ __align__(16) float g_pacc[BB * NHEADS * TSPLIT * HD];

// packed f32x2 fma (Blackwell): d = a*b + c on two lanes
__device__ __forceinline__ unsigned long long fma_f32x2(unsigned long long a,
                                                        unsigned long long b,
                                                        unsigned long long c) {
    unsigned long long d;
    asm("fma.rn.f32x2 %0, %1, %2, %3;" : "=l"(d) : "l"(a), "l"(b), "l"(c));
    return d;
}

__device__ __forceinline__ unsigned long long pack_pair(float lo, float hi) {
    unsigned long long d;
    asm("mov.b64 %0, {%1, %2};" : "=l"(d) : "f"(lo), "f"(hi));
    return d;
}

__device__ __forceinline__ unsigned long long pack2u(unsigned int u) {
    unsigned long long d;
    asm("mov.b64 %0, {%1, %1};" : "=l"(d) : "r"(u));
    return d;
}

__device__ __forceinline__ void cp16(unsigned int smem, const void* gmem) {
    asm volatile("cp.async.cg.shared.global [%0], [%1], 16;" :: "r"(smem), "l"(gmem));
}
#define CP_COMMIT() asm volatile("cp.async.commit_group;" ::: "memory")
#define CP_WAIT(n)  asm volatile("cp.async.wait_group %0;" :: "n"(n) : "memory")

// ---------------- per-warp-staged split-K GEMV (barrier-free mainloop) ----------------
// Block: 512 cols x KCHUNK rows, 256 threads. Each WARP owns a 64-col slice and
// its own 4-slot x (4 rows x 64 floats = 1KB) smem ring: cp.async groups are
// warp-local, synced with CP_WAIT + __syncwarp (no bar.sync convoy). 3 stages
// per warp always in flight -> 6 blocks x 8 warps x 3KB = 144KB in flight/SM.
// x kept as f32x2 batch-pairs [k][j]; row = 1 LDS.64(w) + 2 broadcast LDS.128.
template <int N, int KCHUNK, bool PROJ>
__global__ __launch_bounds__(256) void gemv_warp_kernel(const float* __restrict__ X,
                                                        const float* __restrict__ W) {
    constexpr int NS = KCHUNK / 4;
    __shared__ __align__(16) float wring[8][4][4 * 64];          // 32 KB: [warp][slot][r*64]
    __shared__ __align__(16) unsigned long long xsp[KCHUNK * 4]; // [k][j] batch-pairs

    float* const part = PROJ ? g_proj_part : g_qkv_part;

    const int tid  = threadIdx.x;
    const int wid  = tid >> 5, lane = tid & 31;
    const int col0 = blockIdx.x * 512;
    const int colw = col0 + wid * 64;          // this warp's column slice
    const int k0   = blockIdx.y * KCHUNK;

    // ---- prologue: each warp issues its stages 0..2 ----
#pragma unroll
    for (int s = 0; s < 3; ++s) {
        const float* gp = W + (size_t)(k0 + s * 4) * N + colw;
        const unsigned int sb = (unsigned int)__cvta_generic_to_shared(&wring[wid][s][0]);
#pragma unroll
        for (int i = 0; i < 2; ++i) {
            const int idx = i * 32 + lane;     // 16B chunks within 1KB stage
            const int r = idx >> 4, c = idx & 15;
            cp16(sb + idx * 16, gp + (size_t)r * N + c * 4);
        }
        CP_COMMIT();
    }

    // ---- fill xsp while stages are in flight (block-wide, one barrier total) ----
    if (!PROJ) {
        for (int i = tid; i < KCHUNK * 4; i += 256) {
            const int k = i >> 2, j = i & 3;
            xsp[i] = pack_pair(X[(2 * j) * HDIM + k0 + k],
                               X[(2 * j + 1) * HDIM + k0 + k]);
        }
    } else {
        for (int i = tid; i < KCHUNK * 4; i += 256) {
            const int k = i >> 2, j = i & 3;
            const int hk = k0 + k;
            const int h = hk >> 7, d = hk & (HD - 1);
            float v[2];
#pragma unroll
            for (int bb = 0; bb < 2; ++bb) {
                const int base = ((2 * j + bb) * NHEADS + h) * TSPLIT;
                float M = -CUDART_INF_F;
#pragma unroll
                for (int s = 0; s < TSPLIT; ++s) M = fmaxf(M, g_pm[base + s]);
                float L = 0.f, A = 0.f;
#pragma unroll
                for (int s = 0; s < TSPLIT; ++s) {
                    const float f = __expf(g_pm[base + s] - M);
                    L = fmaf(f, g_pl[base + s], L);
                    A = fmaf(f, g_pacc[(base + s) * HD + d], A);
                }
                v[bb] = A / L;
            }
            xsp[i] = pack_pair(v[0], v[1]);
        }
    }
    __syncthreads();   // xsp visible to all warps; mainloop below is barrier-free

    unsigned long long acc[2][4];
#pragma unroll
    for (int c = 0; c < 2; ++c)
#pragma unroll
        for (int j = 0; j < 4; ++j) acc[c][j] = 0ull;

    for (int s = 0; s < NS; ++s) {
        CP_WAIT(2);        // this warp's stage s complete
        __syncwarp();      // cross-lane visibility; all lanes done reading slot (s-1)&3

        if (s + 3 < NS) {  // refill the slot vacated at iteration s-1
            const float* gp = W + (size_t)(k0 + (s + 3) * 4) * N + colw;
            const unsigned int sb =
                (unsigned int)__cvta_generic_to_shared(&wring[wid][(s + 3) & 3][0]);
#pragma unroll
            for (int i = 0; i < 2; ++i) {
                const int idx = i * 32 + lane;
                const int r = idx >> 4, c = idx & 15;
                cp16(sb + idx * 16, gp + (size_t)r * N + c * 4);
            }
        }
        CP_COMMIT();       // exactly one group per iteration keeps wait-count invariant

        const float* wst = &wring[wid][s & 3][0];
#pragma unroll
        for (int r = 0; r < 4; ++r) {
            const unsigned long long w =
                *reinterpret_cast<const unsigned long long*>(wst + r * 64 + 2 * lane);
            const unsigned long long w00 = pack2u((unsigned int)w);
            const unsigned long long w11 = pack2u((unsigned int)(w >> 32));
            const int k = s * 4 + r;
            const ulonglong2 x01 = *reinterpret_cast<const ulonglong2*>(&xsp[k * 4]);
            const ulonglong2 x23 = *reinterpret_cast<const ulonglong2*>(&xsp[k * 4 + 2]);
            acc[0][0] = fma_f32x2(w00, x01.x, acc[0][0]);
            acc[1][0] = fma_f32x2(w11, x01.x, acc[1][0]);
            acc[0][1] = fma_f32x2(w00, x01.y, acc[0][1]);
            acc[1][1] = fma_f32x2(w11, x01.y, acc[1][1]);
            acc[0][2] = fma_f32x2(w00, x23.x, acc[0][2]);
            acc[1][2] = fma_f32x2(w11, x23.x, acc[1][2]);
            acc[0][3] = fma_f32x2(w00, x23.y, acc[0][3]);
            acc[1][3] = fma_f32x2(w11, x23.y, acc[1][3]);
        }
    }

    // ---- write partials: acc[c][j] lanes = batches (2j, 2j+1), col = colw+2*lane+c
    const size_t base = (size_t)blockIdx.y * BB * N + colw + 2 * lane;
#pragma unroll
    for (int c = 0; c < 2; ++c)
#pragma unroll
        for (int j = 0; j < 4; ++j) {
            const float lo = __uint_as_float((unsigned int)acc[c][j]);
            const float hi = __uint_as_float((unsigned int)(acc[c][j] >> 32));
            part[base + (size_t)(2 * j) * N + c]     = lo;
            part[base + (size_t)(2 * j + 1) * N + c] = hi;
        }
}

// ---------------- deterministic split-K reduce + bias (float4) ----------------
template <int N, int NSPLIT, bool PROJ>
__global__ __launch_bounds__(256) void reduce_bias_kernel(const float* __restrict__ bias,
                                                          float* __restrict__ outp) {
    const int idx4 = blockIdx.x * 256 + threadIdx.x;
    if (idx4 >= BB * N / 4) return;
    const int b = idx4 / (N / 4), j4 = idx4 - b * (N / 4);
    const float* part = PROJ ? g_proj_part : g_qkv_part;
    float4 s = reinterpret_cast<const float4*>(bias)[j4];
#pragma unroll
    for (int p = 0; p < NSPLIT; ++p) {
        const float4 v = *reinterpret_cast<const float4*>(
            part + ((size_t)p * BB + b) * N + 4 * j4);
        s.x += v.x; s.y += v.y; s.z += v.z; s.w += v.w;
    }
    float* out = PROJ ? outp : g_qkv;
    *reinterpret_cast<float4*>(out + b * N + 4 * j4) = s;
}

// ---------------- flash-decode attention partials (two-pass per chunk) ----------------
__global__ __launch_bounds__(128) void attn_partial_kernel(const float* __restrict__ ck,
                                                           const float* __restrict__ cv,
                                                           int P, int T, int chunk) {
    const int bh = blockIdx.x;
    const int b = bh >> 5, h = bh & (NHEADS - 1);
    const int split = blockIdx.y;
    const int t0 = split * chunk;
    const int t1 = min(t0 + chunk, T);

    __shared__ __align__(16) float qs[HD];
    __shared__ float ss[CHUNK_MAX];
    __shared__ float wm[4], wl[4];
    __shared__ __align__(16) float wacc[4][HD];

    const int tid = threadIdx.x, wid = tid >> 5, lane = tid & 31;
    if (tid < HD) qs[tid] = g_qkv[b * N3 + h * HD + tid];
    __syncthreads();

    const float4 q4 = *reinterpret_cast<const float4*>(qs + lane * 4);
    const float scale = 0.08838834764831845f;  // 1/sqrt(128)

    const size_t tstride = (size_t)BB * NHEADS * HD;
    const size_t bhoff = ((size_t)b * NHEADS + h) * HD + lane * 4;
    const float* knew = g_qkv + b * N3 + HDIM     + h * HD + lane * 4;
    const float* vnew = g_qkv + b * N3 + 2 * HDIM + h * HD + lane * 4;

    // ---- pass A: scores ----
    float mloc = -CUDART_INF_F;
#pragma unroll 8
    for (int t = t0 + wid; t < t1; t += 4) {
        const float* kp = (t < P) ? (ck + (size_t)t * tstride + bhoff) : knew;
        const float4 k4 = *reinterpret_cast<const float4*>(kp);
        float s = k4.x * q4.x;
        s = fmaf(k4.y, q4.y, s);
        s = fmaf(k4.z, q4.z, s);
        s = fmaf(k4.w, q4.w, s);
        s += __shfl_xor_sync(0xffffffffu, s, 16);
        s += __shfl_xor_sync(0xffffffffu, s, 8);
        s += __shfl_xor_sync(0xffffffffu, s, 4);
        s += __shfl_xor_sync(0xffffffffu, s, 2);
        s += __shfl_xor_sync(0xffffffffu, s, 1);
        s *= scale;
        mloc = fmaxf(mloc, s);
        if (lane == 0) ss[t - t0] = s;
    }
    if (lane == 0) wm[wid] = mloc;
    __syncthreads();

    const float M = fmaxf(fmaxf(wm[0], wm[1]), fmaxf(wm[2], wm[3]));

    // ---- pass B: weighted V accumulation ----
    float l = 0.f, ax = 0.f, ay = 0.f, az = 0.f, aw = 0.f;
#pragma unroll 8
    for (int t = t0 + wid; t < t1; t += 4) {
        const float* vp = (t < P) ? (cv + (size_t)t * tstride + bhoff) : vnew;
        const float4 v4 = *reinterpret_cast<const float4*>(vp);
        const float p = __expf(ss[t - t0] - M);
        l += p;
        ax = fmaf(p, v4.x, ax);
        ay = fmaf(p, v4.y, ay);
        az = fmaf(p, v4.z, az);
        aw = fmaf(p, v4.w, aw);
    }

    if (lane == 0) wl[wid] = l;
    *reinterpret_cast<float4*>(&wacc[wid][lane * 4]) = make_float4(ax, ay, az, aw);
    __syncthreads();

    if (tid < HD) {
        const float L = (wl[0] + wl[1]) + (wl[2] + wl[3]);
        const float A = (wacc[0][tid] + wacc[1][tid]) + (wacc[2][tid] + wacc[3][tid]);
        const int pi = bh * TSPLIT + split;
        g_pacc[pi * HD + tid] = A;
        if (tid == 0) { g_pm[pi] = M; g_pl[pi] = L; }
    }
}

// ---------------- launcher ----------------
extern "C" void kernel_launch(void* const* d_in, const int* in_sizes, int n_in,
                              void* d_out, int out_size) {
    const float* x     = (const float*)d_in[0];
    const float* ck    = (const float*)d_in[1];
    const float* cv    = (const float*)d_in[2];
    const float* Wqkv  = (const float*)d_in[3];
    const float* bqkv  = (const float*)d_in[4];
    const float* Wproj = (const float*)d_in[5];
    const float* bproj = (const float*)d_in[6];

    const int P = in_sizes[1] / (BB * NHEADS * HD);   // 2047
    const int T = P + 1;
    const int chunk = (T + TSPLIT - 1) / TSPLIT;      // 256

    // 1) qkv = x @ Wqkv (+ bqkv in reduce)
    gemv_warp_kernel<N3, KC1, false><<<dim3(N3 / 512, KS1), 256>>>(x, Wqkv);
    reduce_bias_kernel<N3, KS1, false><<<(BB * N3 / 4 + 255) / 256, 256>>>(bqkv, nullptr);

    // 2) flash-decode attention over cache + new token (no cache copy)
    attn_partial_kernel<<<dim3(BB * NHEADS, TSPLIT), 128>>>(ck, cv, P, T, chunk);

    // 3) out = ctx @ Wproj + bproj (ctx combined in the gemv's xsp fill)
    gemv_warp_kernel<HDIM, KC2, true><<<dim3(HDIM / 512, KS2), 256>>>(nullptr, Wproj);
    reduce_bias_kernel<HDIM, KS2, true><<<(BB * HDIM / 4 + 255) / 256, 256>>>(bproj, (float*)d_out);
}

// round 16
// speedup vs baseline: 1.0721x; 1.0721x over previous
#include <cuda_runtime.h>
#include <math_constants.h>

#define BB      8
#define HDIM    4096
#define NHEADS  32
#define HD      128
#define N3      12288          // 3*HDIM
#define KS1     32             // K-splits for qkv gemm
#define KC1     (HDIM / KS1)   // 128 -> 32 stages of 4 rows
#define KS2     64             // K-splits for proj gemm
#define KC2     (HDIM / KS2)   // 64  -> 16 stages
#define TSPLIT  16             // T-splits for flash decode
#define CHUNK_MAX 128          // ceil(2048 / TSPLIT)
#define NSLOT   6              // per-warp ring slots
#define INFLT   5              // stages in flight per warp

// ---------------- scratch (allocation-free) ----------------
__device__ __align__(16) float g_qkv_part[(size_t)KS1 * BB * N3];    // 12.6 MB
__device__ __align__(16) float g_qkv[BB * N3];
__device__ __align__(16) float g_proj_part[(size_t)KS2 * BB * HDIM]; // 8.4 MB
__device__ __align__(16) float g_pm[BB * NHEADS * TSPLIT];
__device__ __align__(16) float g_pl[BB * NHEADS * TSPLIT];
__device__ __align__(16) float g_pacc[BB * NHEADS * TSPLIT * HD];

// packed f32x2 fma (Blackwell): d = a*b + c on two lanes
__device__ __forceinline__ unsigned long long fma_f32x2(unsigned long long a,
                                                        unsigned long long b,
                                                        unsigned long long c) {
    unsigned long long d;
    asm("fma.rn.f32x2 %0, %1, %2, %3;" : "=l"(d) : "l"(a), "l"(b), "l"(c));
    return d;
}

__device__ __forceinline__ unsigned long long pack_pair(float lo, float hi) {
    unsigned long long d;
    asm("mov.b64 %0, {%1, %2};" : "=l"(d) : "f"(lo), "f"(hi));
    return d;
}

__device__ __forceinline__ unsigned long long pack2u(unsigned int u) {
    unsigned long long d;
    asm("mov.b64 %0, {%1, %1};" : "=l"(d) : "r"(u));
    return d;
}

__device__ __forceinline__ void cp16(unsigned int smem, const void* gmem) {
    asm volatile("cp.async.cg.shared.global [%0], [%1], 16;" :: "r"(smem), "l"(gmem));
}
#define CP_COMMIT() asm volatile("cp.async.commit_group;" ::: "memory")
#define CP_WAIT(n)  asm volatile("cp.async.wait_group %0;" :: "n"(n) : "memory")

// ---------------- per-warp-staged split-K GEMV (deep ring, barrier-free) ----------------
// Block: 512 cols x KCHUNK rows, 256 threads. Each WARP owns a 64-col slice and
// a 6-slot x (4 rows x 64 floats = 1KB) smem ring; CP_WAIT(4) keeps 5 stages
// (5KB) in flight per warp -> ~160KB in flight per SM at 4 resident blocks.
// x kept as f32x2 batch-pairs [k][j]; row = 1 LDS.64(w) + 2 broadcast LDS.128.
template <int N, int KCHUNK, bool PROJ>
__global__ __launch_bounds__(256) void gemv_warp_kernel(const float* __restrict__ X,
                                                        const float* __restrict__ W) {
    constexpr int NS = KCHUNK / 4;
    __shared__ __align__(16) float wring[8][NSLOT][4 * 64];      // 48 KB
    __shared__ __align__(16) unsigned long long xsp[KCHUNK * 4]; // [k][j] batch-pairs

    float* const part = PROJ ? g_proj_part : g_qkv_part;

    const int tid  = threadIdx.x;
    const int wid  = tid >> 5, lane = tid & 31;
    const int col0 = blockIdx.x * 512;
    const int colw = col0 + wid * 64;          // this warp's column slice
    const int k0   = blockIdx.y * KCHUNK;

    // ---- prologue: each warp issues stages 0..INFLT-1 into slots 0..INFLT-1 ----
#pragma unroll
    for (int s = 0; s < INFLT; ++s) {
        const float* gp = W + (size_t)(k0 + s * 4) * N + colw;
        const unsigned int sb = (unsigned int)__cvta_generic_to_shared(&wring[wid][s][0]);
#pragma unroll
        for (int i = 0; i < 2; ++i) {
            const int idx = i * 32 + lane;     // 16B chunks within 1KB stage
            const int r = idx >> 4, c = idx & 15;
            cp16(sb + idx * 16, gp + (size_t)r * N + c * 4);
        }
        CP_COMMIT();
    }

    // ---- fill xsp while stages are in flight (one block barrier total) ----
    if (!PROJ) {
        for (int i = tid; i < KCHUNK * 4; i += 256) {
            const int k = i >> 2, j = i & 3;
            xsp[i] = pack_pair(X[(2 * j) * HDIM + k0 + k],
                               X[(2 * j + 1) * HDIM + k0 + k]);
        }
    } else {
        for (int i = tid; i < KCHUNK * 4; i += 256) {
            const int k = i >> 2, j = i & 3;
            const int hk = k0 + k;
            const int h = hk >> 7, d = hk & (HD - 1);
            float v[2];
#pragma unroll
            for (int bb = 0; bb < 2; ++bb) {
                const int base = ((2 * j + bb) * NHEADS + h) * TSPLIT;
                float M = -CUDART_INF_F;
#pragma unroll
                for (int s = 0; s < TSPLIT; ++s) M = fmaxf(M, g_pm[base + s]);
                float L = 0.f, A = 0.f;
#pragma unroll
                for (int s = 0; s < TSPLIT; ++s) {
                    const float f = __expf(g_pm[base + s] - M);
                    L = fmaf(f, g_pl[base + s], L);
                    A = fmaf(f, g_pacc[(base + s) * HD + d], A);
                }
                v[bb] = A / L;
            }
            xsp[i] = pack_pair(v[0], v[1]);
        }
    }
    __syncthreads();   // xsp visible to all warps; mainloop below is barrier-free

    unsigned long long acc[2][4];
#pragma unroll
    for (int c = 0; c < 2; ++c)
#pragma unroll
        for (int j = 0; j < 4; ++j) acc[c][j] = 0ull;

    int rs = 0, ws = INFLT;    // read slot = s % NSLOT, write slot = (s+INFLT) % NSLOT
    for (int s = 0; s < NS; ++s) {
        CP_WAIT(INFLT - 1);    // this warp's stage s complete
        __syncwarp();          // cross-lane visibility; lanes done with the write slot

        if (s + INFLT < NS) {  // refill into slot vacated INFLT-1 iterations ago
            const float* gp = W + (size_t)(k0 + (s + INFLT) * 4) * N + colw;
            const unsigned int sb =
                (unsigned int)__cvta_generic_to_shared(&wring[wid][ws][0]);
#pragma unroll
            for (int i = 0; i < 2; ++i) {
                const int idx = i * 32 + lane;
                const int r = idx >> 4, c = idx & 15;
                cp16(sb + idx * 16, gp + (size_t)r * N + c * 4);
            }
        }
        CP_COMMIT();           // one group per iteration keeps wait-count invariant

        const float* wst = &wring[wid][rs][0];
#pragma unroll
        for (int r = 0; r < 4; ++r) {
            const unsigned long long w =
                *reinterpret_cast<const unsigned long long*>(wst + r * 64 + 2 * lane);
            const unsigned long long w00 = pack2u((unsigned int)w);
            const unsigned long long w11 = pack2u((unsigned int)(w >> 32));
            const int k = s * 4 + r;
            const ulonglong2 x01 = *reinterpret_cast<const ulonglong2*>(&xsp[k * 4]);
            const ulonglong2 x23 = *reinterpret_cast<const ulonglong2*>(&xsp[k * 4 + 2]);
            acc[0][0] = fma_f32x2(w00, x01.x, acc[0][0]);
            acc[1][0] = fma_f32x2(w11, x01.x, acc[1][0]);
            acc[0][1] = fma_f32x2(w00, x01.y, acc[0][1]);
            acc[1][1] = fma_f32x2(w11, x01.y, acc[1][1]);
            acc[0][2] = fma_f32x2(w00, x23.x, acc[0][2]);
            acc[1][2] = fma_f32x2(w11, x23.x, acc[1][2]);
            acc[0][3] = fma_f32x2(w00, x23.y, acc[0][3]);
            acc[1][3] = fma_f32x2(w11, x23.y, acc[1][3]);
        }
        if (++rs == NSLOT) rs = 0;
        if (++ws == NSLOT) ws = 0;
    }

    // ---- write partials: acc[c][j] lanes = batches (2j, 2j+1), col = colw+2*lane+c
    const size_t base = (size_t)blockIdx.y * BB * N + colw + 2 * lane;
#pragma unroll
    for (int c = 0; c < 2; ++c)
#pragma unroll
        for (int j = 0; j < 4; ++j) {
            const float lo = __uint_as_float((unsigned int)acc[c][j]);
            const float hi = __uint_as_float((unsigned int)(acc[c][j] >> 32));
            part[base + (size_t)(2 * j) * N + c]     = lo;
            part[base + (size_t)(2 * j + 1) * N + c] = hi;
        }
}

// ---------------- deterministic split-K reduce + bias (float4) ----------------
template <int N, int NSPLIT, bool PROJ>
__global__ __launch_bounds__(256) void reduce_bias_kernel(const float* __restrict__ bias,
                                                          float* __restrict__ outp) {
    const int idx4 = blockIdx.x * 256 + threadIdx.x;
    if (idx4 >= BB * N / 4) return;
    const int b = idx4 / (N / 4), j4 = idx4 - b * (N / 4);
    const float* part = PROJ ? g_proj_part : g_qkv_part;
    float4 s = reinterpret_cast<const float4*>(bias)[j4];
#pragma unroll
    for (int p = 0; p < NSPLIT; ++p) {
        const float4 v = *reinterpret_cast<const float4*>(
            part + ((size_t)p * BB + b) * N + 4 * j4);
        s.x += v.x; s.y += v.y; s.z += v.z; s.w += v.w;
    }
    float* out = PROJ ? outp : g_qkv;
    *reinterpret_cast<float4*>(out + b * N + 4 * j4) = s;
}

// ---------------- flash-decode attention partials (two-pass per chunk) ----------------
__global__ __launch_bounds__(128) void attn_partial_kernel(const float* __restrict__ ck,
                                                           const float* __restrict__ cv,
                                                           int P, int T, int chunk) {
    const int bh = blockIdx.x;
    const int b = bh >> 5, h = bh & (NHEADS - 1);
    const int split = blockIdx.y;
    const int t0 = split * chunk;
    const int t1 = min(t0 + chunk, T);

    __shared__ __align__(16) float qs[HD];
    __shared__ float ss[CHUNK_MAX];
    __shared__ float wm[4], wl[4];
    __shared__ __align__(16) float wacc[4][HD];

    const int tid = threadIdx.x, wid = tid >> 5, lane = tid & 31;
    if (tid < HD) qs[tid] = g_qkv[b * N3 + h * HD + tid];
    __syncthreads();

    const float4 q4 = *reinterpret_cast<const float4*>(qs + lane * 4);
    const float scale = 0.08838834764831845f;  // 1/sqrt(128)

    const size_t tstride = (size_t)BB * NHEADS * HD;
    const size_t bhoff = ((size_t)b * NHEADS + h) * HD + lane * 4;
    const float* knew = g_qkv + b * N3 + HDIM     + h * HD + lane * 4;
    const float* vnew = g_qkv + b * N3 + 2 * HDIM + h * HD + lane * 4;

    // ---- pass A: scores ----
    float mloc = -CUDART_INF_F;
#pragma unroll 8
    for (int t = t0 + wid; t < t1; t += 4) {
        const float* kp = (t < P) ? (ck + (size_t)t * tstride + bhoff) : knew;
        const float4 k4 = *reinterpret_cast<const float4*>(kp);
        float s = k4.x * q4.x;
        s = fmaf(k4.y, q4.y, s);
        s = fmaf(k4.z, q4.z, s);
        s = fmaf(k4.w, q4.w, s);
        s += __shfl_xor_sync(0xffffffffu, s, 16);
        s += __shfl_xor_sync(0xffffffffu, s, 8);
        s += __shfl_xor_sync(0xffffffffu, s, 4);
        s += __shfl_xor_sync(0xffffffffu, s, 2);
        s += __shfl_xor_sync(0xffffffffu, s, 1);
        s *= scale;
        mloc = fmaxf(mloc, s);
        if (lane == 0) ss[t - t0] = s;
    }
    if (lane == 0) wm[wid] = mloc;
    __syncthreads();

    const float M = fmaxf(fmaxf(wm[0], wm[1]), fmaxf(wm[2], wm[3]));

    // ---- pass B: weighted V accumulation ----
    float l = 0.f, ax = 0.f, ay = 0.f, az = 0.f, aw = 0.f;
#pragma unroll 8
    for (int t = t0 + wid; t < t1; t += 4) {
        const float* vp = (t < P) ? (cv + (size_t)t * tstride + bhoff) : vnew;
        const float4 v4 = *reinterpret_cast<const float4*>(vp);
        const float p = __expf(ss[t - t0] - M);
        l += p;
        ax = fmaf(p, v4.x, ax);
        ay = fmaf(p, v4.y, ay);
        az = fmaf(p, v4.z, az);
        aw = fmaf(p, v4.w, aw);
    }

    if (lane == 0) wl[wid] = l;
    *reinterpret_cast<float4*>(&wacc[wid][lane * 4]) = make_float4(ax, ay, az, aw);
    __syncthreads();

    if (tid < HD) {
        const float L = (wl[0] + wl[1]) + (wl[2] + wl[3]);
        const float A = (wacc[0][tid] + wacc[1][tid]) + (wacc[2][tid] + wacc[3][tid]);
        const int pi = bh * TSPLIT + split;
        g_pacc[pi * HD + tid] = A;
        if (tid == 0) { g_pm[pi] = M; g_pl[pi] = L; }
    }
}

// ---------------- launcher ----------------
extern "C" void kernel_launch(void* const* d_in, const int* in_sizes, int n_in,
                              void* d_out, int out_size) {
    const float* x     = (const float*)d_in[0];
    const float* ck    = (const float*)d_in[1];
    const float* cv    = (const float*)d_in[2];
    const float* Wqkv  = (const float*)d_in[3];
    const float* bqkv  = (const float*)d_in[4];
    const float* Wproj = (const float*)d_in[5];
    const float* bproj = (const float*)d_in[6];

    const int P = in_sizes[1] / (BB * NHEADS * HD);   // 2047
    const int T = P + 1;
    const int chunk = (T + TSPLIT - 1) / TSPLIT;      // 128

    // 1) qkv = x @ Wqkv (+ bqkv in reduce)
    gemv_warp_kernel<N3, KC1, false><<<dim3(N3 / 512, KS1), 256>>>(x, Wqkv);
    reduce_bias_kernel<N3, KS1, false><<<(BB * N3 / 4 + 255) / 256, 256>>>(bqkv, nullptr);

    // 2) flash-decode attention over cache + new token (no cache copy)
    attn_partial_kernel<<<dim3(BB * NHEADS, TSPLIT), 128>>>(ck, cv, P, T, chunk);

    // 3) out = ctx @ Wproj + bproj (ctx combined in the gemv's xsp fill)
    gemv_warp_kernel<HDIM, KC2, true><<<dim3(HDIM / 512, KS2), 256>>>(nullptr, Wproj);
    reduce_bias_kernel<HDIM, KS2, true><<<(BB * HDIM / 4 + 255) / 256, 256>>>(bproj, (float*)d_out);
}